// round 1
// baseline (speedup 1.0000x reference)
#include <cuda_runtime.h>
#include <cuda_bf16.h>

#define TOKENS 32768
#define DM 2048
#define NE 64
#define TB 64       // tokens per block
#define KT 32       // k-tile
#define XST 36      // padded smem row stride (floats): 144B rows, 16B aligned, conflict-limited

__global__ __launch_bounds__(256) void router_kernel(
    const float* __restrict__ x,
    const float* __restrict__ Wr,
    float* __restrict__ out)
{
    __shared__ float xs[TB][XST];       // x tile   [token][k]
    __shared__ float ws[NE][XST];       // W tile   [expert][k]
    __shared__ float lg[TB][NE + 1];    // logits -> exp values; col NE holds 1/sum

    const int tid  = threadIdx.x;
    const int tok0 = blockIdx.x * TB;
    const int tr   = tid >> 4;          // 0..15  (token group)
    const int tc   = tid & 15;          // 0..15  (expert group)

    float acc[4][4];
    #pragma unroll
    for (int i = 0; i < 4; i++)
        #pragma unroll
        for (int j = 0; j < 4; j++) acc[i][j] = 0.f;

    const int lrow = tid >> 3;            // 0..31
    const int lcol = (tid & 7) * 4;       // 0,4,...,28

    for (int k0 = 0; k0 < DM; k0 += KT) {
        // Cooperative load: 64x32 floats of x and of W, fully coalesced float4.
        #pragma unroll
        for (int it = 0; it < 2; it++) {
            const int row = lrow + it * 32;
            float4 vx = *reinterpret_cast<const float4*>(
                &x[(size_t)(tok0 + row) * DM + k0 + lcol]);
            *reinterpret_cast<float4*>(&xs[row][lcol]) = vx;
            float4 vw = *reinterpret_cast<const float4*>(
                &Wr[(size_t)row * DM + k0 + lcol]);
            *reinterpret_cast<float4*>(&ws[row][lcol]) = vw;
        }
        __syncthreads();

        #pragma unroll
        for (int kk = 0; kk < KT; kk += 4) {
            float4 a[4], b[4];
            #pragma unroll
            for (int i = 0; i < 4; i++)
                a[i] = *reinterpret_cast<const float4*>(&xs[tr * 4 + i][kk]);
            #pragma unroll
            for (int j = 0; j < 4; j++)
                b[j] = *reinterpret_cast<const float4*>(&ws[tc * 4 + j][kk]);
            #pragma unroll
            for (int i = 0; i < 4; i++)
                #pragma unroll
                for (int j = 0; j < 4; j++) {
                    acc[i][j] += a[i].x * b[j].x;
                    acc[i][j] += a[i].y * b[j].y;
                    acc[i][j] += a[i].z * b[j].z;
                    acc[i][j] += a[i].w * b[j].w;
                }
        }
        __syncthreads();
    }

    // Stash logits tile in shared memory.
    #pragma unroll
    for (int i = 0; i < 4; i++)
        #pragma unroll
        for (int j = 0; j < 4; j++)
            lg[tr * 4 + i][tc * 4 + j] = acc[i][j];
    __syncthreads();

    float* gates = out;                               // [TOKENS, 2]
    float* idxo  = out + (size_t)TOKENS * 2;          // [TOKENS, 2] (indices as float)
    float* probs = out + (size_t)TOKENS * 4;          // [TOKENS, 64]

    // Per-token softmax + top-2 (threads 0..63, one token each; conflict-free row scan).
    if (tid < TB) {
        const int t = tid;
        float m = -1e30f;
        #pragma unroll
        for (int e = 0; e < NE; e++) m = fmaxf(m, lg[t][e]);

        float s = 0.f;
        float b1 = -1e30f, b2 = -1e30f;
        int   i1 = 0,      i2 = 0;
        #pragma unroll
        for (int e = 0; e < NE; e++) {
            const float l = lg[t][e];
            const float p = __expf(l - m);
            s += p;
            lg[t][e] = p;               // unnormalized prob, normalized at writeout
            if (l > b1)      { b2 = b1; i2 = i1; b1 = l; i1 = e; }
            else if (l > b2) { b2 = l;  i2 = e; }
        }
        lg[t][NE] = 1.f / s;            // stash inverse sum for the writeout phase

        const float e1 = __expf(b1 - m);
        const float e2 = __expf(b2 - m);
        const float gs = 1.f / (e1 + e2);   // softmax denom cancels in renorm
        const size_t tg = (size_t)(tok0 + t);
        gates[tg * 2 + 0] = e1 * gs;
        gates[tg * 2 + 1] = e2 * gs;
        idxo [tg * 2 + 0] = (float)i1;
        idxo [tg * 2 + 1] = (float)i2;
    }
    __syncthreads();

    // Coalesced router_probs writeout: 64x64 floats = 1024 float4, 4 per thread.
    #pragma unroll
    for (int it = 0; it < 4; it++) {
        const int p  = tid + it * 256;
        const int t  = p >> 4;
        const int e4 = (p & 15) * 4;
        const float inv = lg[t][NE];
        float4 v;
        v.x = lg[t][e4 + 0] * inv;
        v.y = lg[t][e4 + 1] * inv;
        v.z = lg[t][e4 + 2] * inv;
        v.w = lg[t][e4 + 3] * inv;
        *reinterpret_cast<float4*>(&probs[((size_t)(tok0 + t)) * NE + e4]) = v;
    }
}

extern "C" void kernel_launch(void* const* d_in, const int* in_sizes, int n_in,
                              void* d_out, int out_size) {
    const float* x  = (const float*)d_in[0];   // [32768, 2048] fp32
    const float* Wr = (const float*)d_in[1];   // [64, 2048] fp32
    float* out = (float*)d_out;
    router_kernel<<<TOKENS / TB, 256>>>(x, Wr, out);
}

// round 4
// speedup vs baseline: 4.7053x; 4.7053x over previous
#include <cuda_runtime.h>
#include <cuda_bf16.h>
#include <cstdint>

#define TOKENS 32768
#define DM     2048
#define NE     64
#define TM     128          // tokens per CTA
#define KT     32           // k per tile
#define NT     (DM / KT)    // 64 tiles
#define PADB   72           // padded smem row stride in bytes (36 bf16)

// per-stage smem byte offsets
#define XHI   0
#define XLO   9216          // 128*72
#define WHI   18432
#define WLO   23040         // +64*72
#define STAGE 27648
#define SMEM_TOTAL (2 * STAGE)   // 55296

__device__ __forceinline__ uint32_t smem_u32(const void* p) {
    uint32_t a;
    asm("{ .reg .u64 t; cvta.to.shared.u64 t, %1; cvt.u32.u64 %0, t; }" : "=r"(a) : "l"(p));
    return a;
}
__device__ __forceinline__ uint32_t lds32(uint32_t a) {
    uint32_t v;
    asm volatile("ld.shared.b32 %0, [%1];" : "=r"(v) : "r"(a));
    return v;
}
__device__ __forceinline__ void mma16816(float* d, const uint32_t* a,
                                         uint32_t b0, uint32_t b1) {
    asm volatile(
        "mma.sync.aligned.m16n8k16.row.col.f32.bf16.bf16.f32 "
        "{%0,%1,%2,%3}, {%4,%5,%6,%7}, {%8,%9}, {%0,%1,%2,%3};"
        : "+f"(d[0]), "+f"(d[1]), "+f"(d[2]), "+f"(d[3])
        : "r"(a[0]), "r"(a[1]), "r"(a[2]), "r"(a[3]), "r"(b0), "r"(b1));
}

// Split float4 into bf16 hi/lo pairs; store 8B each to smem.
__device__ __forceinline__ void split_store(uint32_t hi_addr, uint32_t lo_addr, float4 v) {
    uint32_t h01, h23, l01, l23;
    asm("cvt.rn.bf16x2.f32 %0, %1, %2;" : "=r"(h01) : "f"(v.y), "f"(v.x));
    asm("cvt.rn.bf16x2.f32 %0, %1, %2;" : "=r"(h23) : "f"(v.w), "f"(v.z));
    float r0 = v.x - __uint_as_float((h01 & 0xFFFFu) << 16);
    float r1 = v.y - __uint_as_float(h01 & 0xFFFF0000u);
    float r2 = v.z - __uint_as_float((h23 & 0xFFFFu) << 16);
    float r3 = v.w - __uint_as_float(h23 & 0xFFFF0000u);
    asm("cvt.rn.bf16x2.f32 %0, %1, %2;" : "=r"(l01) : "f"(r1), "f"(r0));
    asm("cvt.rn.bf16x2.f32 %0, %1, %2;" : "=r"(l23) : "f"(r3), "f"(r2));
    asm volatile("st.shared.v2.b32 [%0], {%1, %2};" :: "r"(hi_addr), "r"(h01), "r"(h23));
    asm volatile("st.shared.v2.b32 [%0], {%1, %2};" :: "r"(lo_addr), "r"(l01), "r"(l23));
}

__device__ __forceinline__ bool better(float v, int i, float bv, int bi) {
    return (v > bv) || (v == bv && i < bi);
}

__global__ __launch_bounds__(256, 2) void router_mma_kernel(
    const float* __restrict__ x,
    const float* __restrict__ Wr,
    float* __restrict__ out)
{
    extern __shared__ char smem[];
    const uint32_t sb = smem_u32(smem);
    const int tid  = threadIdx.x;
    const int wid  = tid >> 5;
    const int lane = tid & 31;
    const int lr   = lane >> 2;     // groupID: row within 16-row block / n within 8-col block
    const int q    = lane & 3;      // threadID in group

    float acc[8][4];
    #pragma unroll
    for (int nb = 0; nb < 8; nb++)
        #pragma unroll
        for (int j = 0; j < 4; j++) acc[nb][j] = 0.f;

    const float* xg = x + (size_t)blockIdx.x * TM * DM;

    float4 vx[4], vw[2];

    // fragment smem base offsets (within stage)
    const uint32_t aoff = (uint32_t)(wid * 16 + lr) * PADB + q * 4;   // + XHI/XLO
    const uint32_t boff = (uint32_t)lr * PADB + q * 4;                // + WHI/WLO (+nb*576)

    // ---- preload + stage tile 0 ----
    #pragma unroll
    for (int i = 0; i < 4; i++) {
        const int idx = tid + i * 256;
        vx[i] = *reinterpret_cast<const float4*>(xg + (size_t)(idx >> 3) * DM + (idx & 7) * 4);
    }
    #pragma unroll
    for (int i = 0; i < 2; i++) {
        const int idx = tid + i * 256;
        vw[i] = *reinterpret_cast<const float4*>(Wr + (size_t)(idx >> 3) * DM + (idx & 7) * 4);
    }
    {
        const uint32_t st = sb;
        #pragma unroll
        for (int i = 0; i < 4; i++) {
            const int idx = tid + i * 256;
            const uint32_t o = (uint32_t)(idx >> 3) * PADB + (uint32_t)(idx & 7) * 8;
            split_store(st + XHI + o, st + XLO + o, vx[i]);
        }
        #pragma unroll
        for (int i = 0; i < 2; i++) {
            const int idx = tid + i * 256;
            const uint32_t o = (uint32_t)(idx >> 3) * PADB + (uint32_t)(idx & 7) * 8;
            split_store(st + WHI + o, st + WLO + o, vw[i]);
        }
    }
    __syncthreads();

    #pragma unroll 1
    for (int t = 0; t < NT; t++) {
        const uint32_t st = sb + (uint32_t)(t & 1) * STAGE;

        // issue global loads for tile t+1 (latency hidden behind MMAs)
        if (t + 1 < NT) {
            const int k0 = (t + 1) * KT;
            #pragma unroll
            for (int i = 0; i < 4; i++) {
                const int idx = tid + i * 256;
                vx[i] = *reinterpret_cast<const float4*>(
                    xg + (size_t)(idx >> 3) * DM + k0 + (idx & 7) * 4);
            }
            #pragma unroll
            for (int i = 0; i < 2; i++) {
                const int idx = tid + i * 256;
                vw[i] = *reinterpret_cast<const float4*>(
                    Wr + (size_t)(idx >> 3) * DM + k0 + (idx & 7) * 4);
            }
        }

        // MMAs on tile t
        #pragma unroll
        for (int kk = 0; kk < KT; kk += 16) {
            const uint32_t ko = (uint32_t)kk * 2;
            uint32_t ah[4], al[4];
            const uint32_t ab = st + aoff + ko;
            ah[0] = lds32(ab + XHI);        ah[1] = lds32(ab + XHI + 576);
            ah[2] = lds32(ab + XHI + 16);   ah[3] = lds32(ab + XHI + 592);
            al[0] = lds32(ab + XLO);        al[1] = lds32(ab + XLO + 576);
            al[2] = lds32(ab + XLO + 16);   al[3] = lds32(ab + XLO + 592);
            #pragma unroll
            for (int nb = 0; nb < 8; nb++) {
                const uint32_t bb = st + boff + (uint32_t)nb * 576 + ko;
                const uint32_t bh0 = lds32(bb + WHI);
                const uint32_t bh1 = lds32(bb + WHI + 16);
                const uint32_t bl0 = lds32(bb + WLO);
                const uint32_t bl1 = lds32(bb + WLO + 16);
                mma16816(acc[nb], ah, bh0, bh1);   // hi*hi
                mma16816(acc[nb], ah, bl0, bl1);   // hi*lo
                mma16816(acc[nb], al, bh0, bh1);   // lo*hi
            }
        }

        // stage tile t+1 into the other buffer
        if (t + 1 < NT) {
            const uint32_t sn = sb + (uint32_t)((t + 1) & 1) * STAGE;
            #pragma unroll
            for (int i = 0; i < 4; i++) {
                const int idx = tid + i * 256;
                const uint32_t o = (uint32_t)(idx >> 3) * PADB + (uint32_t)(idx & 7) * 8;
                split_store(sn + XHI + o, sn + XLO + o, vx[i]);
            }
            #pragma unroll
            for (int i = 0; i < 2; i++) {
                const int idx = tid + i * 256;
                const uint32_t o = (uint32_t)(idx >> 3) * PADB + (uint32_t)(idx & 7) * 8;
                split_store(sn + WHI + o, sn + WLO + o, vw[i]);
            }
        }
        __syncthreads();
    }

    // ---- epilogue: register-resident softmax + top-2 ----
    float* gates = out;                        // [TOKENS, 2]
    float* idxo  = out + (size_t)TOKENS * 2;   // [TOKENS, 2] indices as float
    float* probs = out + (size_t)TOKENS * 4;   // [TOKENS, 64]

    #pragma unroll
    for (int rs = 0; rs < 2; rs++) {           // rs=0: row lr, rs=1: row lr+8
        const int tok = blockIdx.x * TM + wid * 16 + lr + rs * 8;

        float m = -1e30f;
        #pragma unroll
        for (int nb = 0; nb < 8; nb++) {
            m = fmaxf(m, acc[nb][rs * 2 + 0]);
            m = fmaxf(m, acc[nb][rs * 2 + 1]);
        }
        m = fmaxf(m, __shfl_xor_sync(0xffffffffu, m, 1));
        m = fmaxf(m, __shfl_xor_sync(0xffffffffu, m, 2));

        float e[16];
        float s = 0.f;
        #pragma unroll
        for (int nb = 0; nb < 8; nb++) {
            e[nb * 2 + 0] = __expf(acc[nb][rs * 2 + 0] - m);
            e[nb * 2 + 1] = __expf(acc[nb][rs * 2 + 1] - m);
            s += e[nb * 2 + 0] + e[nb * 2 + 1];
        }
        s += __shfl_xor_sync(0xffffffffu, s, 1);
        s += __shfl_xor_sync(0xffffffffu, s, 2);
        const float inv = 1.f / s;

        // local top-2 (cols nb*8 + q*2 + jj)
        float b1 = -1e30f, b2 = -1e30f;
        int   i1 = 0x7fffffff, i2 = 0x7fffffff;
        #pragma unroll
        for (int nb = 0; nb < 8; nb++) {
            #pragma unroll
            for (int jj = 0; jj < 2; jj++) {
                const float v = acc[nb][rs * 2 + jj];
                const int   c = nb * 8 + q * 2 + jj;
                if (better(v, c, b1, i1)) { b2 = b1; i2 = i1; b1 = v; i1 = c; }
                else if (better(v, c, b2, i2)) { b2 = v; i2 = c; }
            }
        }
        // merge across the quad
        #pragma unroll
        for (int d = 1; d <= 2; d <<= 1) {
            const float p1 = __shfl_xor_sync(0xffffffffu, b1, d);
            const int  pi1 = __shfl_xor_sync(0xffffffffu, i1, d);
            const float p2 = __shfl_xor_sync(0xffffffffu, b2, d);
            const int  pi2 = __shfl_xor_sync(0xffffffffu, i2, d);
            if (better(p1, pi1, b1, i1)) {
                if (better(b1, i1, p2, pi2)) { b2 = b1; i2 = i1; }
                else                          { b2 = p2; i2 = pi2; }
                b1 = p1; i1 = pi1;
            } else if (better(p1, pi1, b2, i2)) {
                b2 = p1; i2 = pi1;
            }
        }

        if (q == 0) {
            const float e1 = __expf(b1 - m);
            const float e2 = __expf(b2 - m);
            const float gs = 1.f / (e1 + e2);
            *reinterpret_cast<float2*>(&gates[(size_t)tok * 2]) = make_float2(e1 * gs, e2 * gs);
            *reinterpret_cast<float2*>(&idxo [(size_t)tok * 2]) = make_float2((float)i1, (float)i2);
        }

        #pragma unroll
        for (int nb = 0; nb < 8; nb++) {
            *reinterpret_cast<float2*>(&probs[(size_t)tok * NE + nb * 8 + q * 2]) =
                make_float2(e[nb * 2 + 0] * inv, e[nb * 2 + 1] * inv);
        }
    }
}

extern "C" void kernel_launch(void* const* d_in, const int* in_sizes, int n_in,
                              void* d_out, int out_size) {
    const float* x  = (const float*)d_in[0];
    const float* Wr = (const float*)d_in[1];
    float* out = (float*)d_out;
    cudaFuncSetAttribute(router_mma_kernel,
                         cudaFuncAttributeMaxDynamicSharedMemorySize, SMEM_TOTAL);
    router_mma_kernel<<<TOKENS / TM, 256, SMEM_TOTAL>>>(x, Wr, out);
}

// round 6
// speedup vs baseline: 4.7105x; 1.0011x over previous
#include <cuda_runtime.h>
#include <cuda_bf16.h>
#include <cstdint>

#define TOKENS 32768
#define DM     2048
#define NE     64
#define TM     128          // tokens per CTA
#define KT     32           // k per tile
#define NT     (DM / KT)    // 64 tiles
#define PADB   72           // padded smem row stride in bytes (36 bf16)

// per-stage smem byte offsets
#define XHI   0
#define XLO   9216          // 128*72
#define WHI   18432
#define WLO   23040         // +64*72
#define STAGE 27648
#define SMEM_TOTAL (2 * STAGE)   // 55296

__device__ __forceinline__ uint32_t smem_u32(const void* p) {
    uint32_t a;
    asm("{ .reg .u64 t; cvta.to.shared.u64 t, %1; cvt.u32.u64 %0, t; }" : "=r"(a) : "l"(p));
    return a;
}
__device__ __forceinline__ uint32_t lds32(uint32_t a) {
    uint32_t v;
    asm volatile("ld.shared.b32 %0, [%1];" : "=r"(v) : "r"(a));
    return v;
}
__device__ __forceinline__ void mma16816(float* d, const uint32_t* a,
                                         uint32_t b0, uint32_t b1) {
    asm volatile(
        "mma.sync.aligned.m16n8k16.row.col.f32.bf16.bf16.f32 "
        "{%0,%1,%2,%3}, {%4,%5,%6,%7}, {%8,%9}, {%0,%1,%2,%3};"
        : "+f"(d[0]), "+f"(d[1]), "+f"(d[2]), "+f"(d[3])
        : "r"(a[0]), "r"(a[1]), "r"(a[2]), "r"(a[3]), "r"(b0), "r"(b1));
}

// Split float4 into bf16 hi/lo pairs; store 8B each to smem.
__device__ __forceinline__ void split_store(uint32_t hi_addr, uint32_t lo_addr, float4 v) {
    uint32_t h01, h23, l01, l23;
    asm("cvt.rn.bf16x2.f32 %0, %1, %2;" : "=r"(h01) : "f"(v.y), "f"(v.x));
    asm("cvt.rn.bf16x2.f32 %0, %1, %2;" : "=r"(h23) : "f"(v.w), "f"(v.z));
    float r0 = v.x - __uint_as_float((h01 & 0xFFFFu) << 16);
    float r1 = v.y - __uint_as_float(h01 & 0xFFFF0000u);
    float r2 = v.z - __uint_as_float((h23 & 0xFFFFu) << 16);
    float r3 = v.w - __uint_as_float(h23 & 0xFFFF0000u);
    asm("cvt.rn.bf16x2.f32 %0, %1, %2;" : "=r"(l01) : "f"(r1), "f"(r0));
    asm("cvt.rn.bf16x2.f32 %0, %1, %2;" : "=r"(l23) : "f"(r3), "f"(r2));
    asm volatile("st.shared.v2.b32 [%0], {%1, %2};" :: "r"(hi_addr), "r"(h01), "r"(h23));
    asm volatile("st.shared.v2.b32 [%0], {%1, %2};" :: "r"(lo_addr), "r"(l01), "r"(l23));
}

__device__ __forceinline__ bool better(float v, int i, float bv, int bi) {
    return (v > bv) || (v == bv && i < bi);
}

__global__ __launch_bounds__(256, 2) void router_mma_kernel(
    const float* __restrict__ x,
    const float* __restrict__ Wr,
    float* __restrict__ out)
{
    extern __shared__ char smem[];
    const uint32_t sb = smem_u32(smem);
    const int tid  = threadIdx.x;
    const int wid  = tid >> 5;
    const int lane = tid & 31;
    const int lr   = lane >> 2;     // groupID: row within 16-row block / n within 8-col block
    const int q    = lane & 3;      // threadID in group

    float acc[8][4];
    #pragma unroll
    for (int nb = 0; nb < 8; nb++)
        #pragma unroll
        for (int j = 0; j < 4; j++) acc[nb][j] = 0.f;

    const float* xg = x + (size_t)blockIdx.x * TM * DM;

    float4 vx[4], vw[2];

    // fragment smem base offsets (within stage)
    const uint32_t aoff = (uint32_t)(wid * 16 + lr) * PADB + q * 4;   // + XHI/XLO
    const uint32_t boff = (uint32_t)lr * PADB + q * 4;                // + WHI/WLO (+nb*576)

    // ---- preload + stage tile 0 ----
    #pragma unroll
    for (int i = 0; i < 4; i++) {
        const int idx = tid + i * 256;
        vx[i] = *reinterpret_cast<const float4*>(xg + (size_t)(idx >> 3) * DM + (idx & 7) * 4);
    }
    #pragma unroll
    for (int i = 0; i < 2; i++) {
        const int idx = tid + i * 256;
        vw[i] = *reinterpret_cast<const float4*>(Wr + (size_t)(idx >> 3) * DM + (idx & 7) * 4);
    }
    {
        const uint32_t st = sb;
        #pragma unroll
        for (int i = 0; i < 4; i++) {
            const int idx = tid + i * 256;
            const uint32_t o = (uint32_t)(idx >> 3) * PADB + (uint32_t)(idx & 7) * 8;
            split_store(st + XHI + o, st + XLO + o, vx[i]);
        }
        #pragma unroll
        for (int i = 0; i < 2; i++) {
            const int idx = tid + i * 256;
            const uint32_t o = (uint32_t)(idx >> 3) * PADB + (uint32_t)(idx & 7) * 8;
            split_store(st + WHI + o, st + WLO + o, vw[i]);
        }
    }
    __syncthreads();

    #pragma unroll 1
    for (int t = 0; t < NT; t++) {
        const uint32_t st = sb + (uint32_t)(t & 1) * STAGE;

        // issue global loads for tile t+1 (latency hidden behind MMAs)
        if (t + 1 < NT) {
            const int k0 = (t + 1) * KT;
            #pragma unroll
            for (int i = 0; i < 4; i++) {
                const int idx = tid + i * 256;
                vx[i] = *reinterpret_cast<const float4*>(
                    xg + (size_t)(idx >> 3) * DM + k0 + (idx & 7) * 4);
            }
            #pragma unroll
            for (int i = 0; i < 2; i++) {
                const int idx = tid + i * 256;
                vw[i] = *reinterpret_cast<const float4*>(
                    Wr + (size_t)(idx >> 3) * DM + k0 + (idx & 7) * 4);
            }
        }

        // MMAs on tile t
        #pragma unroll
        for (int kk = 0; kk < KT; kk += 16) {
            const uint32_t ko = (uint32_t)kk * 2;
            uint32_t ah[4], al[4];
            const uint32_t ab = st + aoff + ko;
            ah[0] = lds32(ab + XHI);        ah[1] = lds32(ab + XHI + 576);
            ah[2] = lds32(ab + XHI + 16);   ah[3] = lds32(ab + XHI + 592);
            al[0] = lds32(ab + XLO);        al[1] = lds32(ab + XLO + 576);
            al[2] = lds32(ab + XLO + 16);   al[3] = lds32(ab + XLO + 592);
            #pragma unroll
            for (int nb = 0; nb < 8; nb++) {
                const uint32_t bb = st + boff + (uint32_t)nb * 576 + ko;
                const uint32_t bh0 = lds32(bb + WHI);
                const uint32_t bh1 = lds32(bb + WHI + 16);
                const uint32_t bl0 = lds32(bb + WLO);
                const uint32_t bl1 = lds32(bb + WLO + 16);
                mma16816(acc[nb], ah, bh0, bh1);   // hi*hi
                mma16816(acc[nb], ah, bl0, bl1);   // hi*lo
                mma16816(acc[nb], al, bh0, bh1);   // lo*hi
            }
        }

        // stage tile t+1 into the other buffer
        if (t + 1 < NT) {
            const uint32_t sn = sb + (uint32_t)((t + 1) & 1) * STAGE;
            #pragma unroll
            for (int i = 0; i < 4; i++) {
                const int idx = tid + i * 256;
                const uint32_t o = (uint32_t)(idx >> 3) * PADB + (uint32_t)(idx & 7) * 8;
                split_store(sn + XHI + o, sn + XLO + o, vx[i]);
            }
            #pragma unroll
            for (int i = 0; i < 2; i++) {
                const int idx = tid + i * 256;
                const uint32_t o = (uint32_t)(idx >> 3) * PADB + (uint32_t)(idx & 7) * 8;
                split_store(sn + WHI + o, sn + WLO + o, vw[i]);
            }
        }
        __syncthreads();
    }

    // ---- epilogue: register-resident softmax + top-2 ----
    float* gates = out;                        // [TOKENS, 2]
    float* idxo  = out + (size_t)TOKENS * 2;   // [TOKENS, 2] indices as float
    float* probs = out + (size_t)TOKENS * 4;   // [TOKENS, 64]

    #pragma unroll
    for (int rs = 0; rs < 2; rs++) {           // rs=0: row lr, rs=1: row lr+8
        const int tok = blockIdx.x * TM + wid * 16 + lr + rs * 8;

        float m = -1e30f;
        #pragma unroll
        for (int nb = 0; nb < 8; nb++) {
            m = fmaxf(m, acc[nb][rs * 2 + 0]);
            m = fmaxf(m, acc[nb][rs * 2 + 1]);
        }
        m = fmaxf(m, __shfl_xor_sync(0xffffffffu, m, 1));
        m = fmaxf(m, __shfl_xor_sync(0xffffffffu, m, 2));

        float e[16];
        float s = 0.f;
        #pragma unroll
        for (int nb = 0; nb < 8; nb++) {
            e[nb * 2 + 0] = __expf(acc[nb][rs * 2 + 0] - m);
            e[nb * 2 + 1] = __expf(acc[nb][rs * 2 + 1] - m);
            s += e[nb * 2 + 0] + e[nb * 2 + 1];
        }
        s += __shfl_xor_sync(0xffffffffu, s, 1);
        s += __shfl_xor_sync(0xffffffffu, s, 2);
        const float inv = 1.f / s;

        // local top-2 (cols nb*8 + q*2 + jj)
        float b1 = -1e30f, b2 = -1e30f;
        int   i1 = 0x7fffffff, i2 = 0x7fffffff;
        #pragma unroll
        for (int nb = 0; nb < 8; nb++) {
            #pragma unroll
            for (int jj = 0; jj < 2; jj++) {
                const float v = acc[nb][rs * 2 + jj];
                const int   c = nb * 8 + q * 2 + jj;
                if (better(v, c, b1, i1)) { b2 = b1; i2 = i1; b1 = v; i1 = c; }
                else if (better(v, c, b2, i2)) { b2 = v; i2 = c; }
            }
        }
        // merge across the quad
        #pragma unroll
        for (int d = 1; d <= 2; d <<= 1) {
            const float p1 = __shfl_xor_sync(0xffffffffu, b1, d);
            const int  pi1 = __shfl_xor_sync(0xffffffffu, i1, d);
            const float p2 = __shfl_xor_sync(0xffffffffu, b2, d);
            const int  pi2 = __shfl_xor_sync(0xffffffffu, i2, d);
            if (better(p1, pi1, b1, i1)) {
                if (better(b1, i1, p2, pi2)) { b2 = b1; i2 = i1; }
                else                          { b2 = p2; i2 = pi2; }
                b1 = p1; i1 = pi1;
            } else if (better(p1, pi1, b2, i2)) {
                b2 = p1; i2 = pi1;
            }
        }

        if (q == 0) {
            const float e1 = __expf(b1 - m);
            const float e2 = __expf(b2 - m);
            const float gs = 1.f / (e1 + e2);
            *reinterpret_cast<float2*>(&gates[(size_t)tok * 2]) = make_float2(e1 * gs, e2 * gs);
            *reinterpret_cast<float2*>(&idxo [(size_t)tok * 2]) = make_float2((float)i1, (float)i2);
        }

        #pragma unroll
        for (int nb = 0; nb < 8; nb++) {
            *reinterpret_cast<float2*>(&probs[(size_t)tok * NE + nb * 8 + q * 2]) =
                make_float2(e[nb * 2 + 0] * inv, e[nb * 2 + 1] * inv);
        }
    }
}

extern "C" void kernel_launch(void* const* d_in, const int* in_sizes, int n_in,
                              void* d_out, int out_size) {
    const float* x  = (const float*)d_in[0];
    const float* Wr = (const float*)d_in[1];
    float* out = (float*)d_out;
    cudaFuncSetAttribute(router_mma_kernel,
                         cudaFuncAttributeMaxDynamicSharedMemorySize, SMEM_TOTAL);
    router_mma_kernel<<<TOKENS / TM, 256, SMEM_TOTAL>>>(x, Wr, out);
}